// round 2
// baseline (speedup 1.0000x reference)
#include <cuda_runtime.h>
#include <math.h>

#define SLICE 32768      // 512*64 floats per (b,f) slice
#define NTHREADS 512
#define NSLICES 64       // B*C = 4*16

// Scratch: 5 rotation buffers + accumulator per slice (static device memory, no allocs)
__device__ float g_bufs[(size_t)NSLICES * 5 * SLICE];
__device__ float g_acc[(size_t)NSLICES * SLICE];

// ---------------- block reduction ----------------
__device__ __forceinline__ float block_sum(float v, float* red) {
    #pragma unroll
    for (int o = 16; o; o >>= 1) v += __shfl_xor_sync(0xffffffffu, v, o);
    int w = threadIdx.x >> 5, l = threadIdx.x & 31;
    if (l == 0) red[w] = v;
    __syncthreads();
    if (w == 0) {
        float t = (l < 16) ? red[l] : 0.f;
        #pragma unroll
        for (int o = 8; o; o >>= 1) t += __shfl_xor_sync(0xffffffffu, t, o);
        if (l == 0) red[0] = t;
    }
    __syncthreads();
    float r = red[0];
    __syncthreads();
    return r;
}

// ---------------- one basis step ----------------
// dst[n,t] = normalize( A@Bm - (A@Bm . last) last - (A@Bm . sec) sec )
// Also: acc += th * dst.
// A: [512, K] row-major with leading dim lda ; Bm: [K, 64] row-major contiguous.
__device__ void basis_step(const float* __restrict__ A, int lda, int K,
                           const float* __restrict__ Bm,
                           float* __restrict__ dst,
                           const float* __restrict__ lastb,
                           const float* __restrict__ secb,
                           float th, float* __restrict__ acc,
                           float (*As)[512], float (*Bs)[64], float* red)
{
    const int tid = threadIdx.x;
    const int n0 = (tid >> 3) << 3;   // 64 groups of 8 rows
    const int t0 = (tid & 7) << 3;    // 8 groups of 8 cols

    float av[8][8];
    #pragma unroll
    for (int i = 0; i < 8; i++)
        #pragma unroll
        for (int j = 0; j < 8; j++) av[i][j] = 0.f;

    for (int kt = 0; kt < K; kt += 16) {
        // A tile: As[k][n] = A[n][kt+k]  (thread tid loads its own row)
        const float* ar = A + (size_t)tid * lda + kt;
        float4 a0 = *(const float4*)(ar);
        float4 a1 = *(const float4*)(ar + 4);
        float4 a2 = *(const float4*)(ar + 8);
        float4 a3 = *(const float4*)(ar + 12);
        As[0][tid] = a0.x;  As[1][tid] = a0.y;  As[2][tid] = a0.z;  As[3][tid] = a0.w;
        As[4][tid] = a1.x;  As[5][tid] = a1.y;  As[6][tid] = a1.z;  As[7][tid] = a1.w;
        As[8][tid] = a2.x;  As[9][tid] = a2.y;  As[10][tid] = a2.z; As[11][tid] = a2.w;
        As[12][tid] = a3.x; As[13][tid] = a3.y; As[14][tid] = a3.z; As[15][tid] = a3.w;
        // B tile: 16x64 floats, contiguous copy
        if (tid < 256)
            ((float4*)&Bs[0][0])[tid] = ((const float4*)(Bm + (size_t)kt * 64))[tid];
        __syncthreads();

        #pragma unroll
        for (int k = 0; k < 16; k++) {
            float4 aa0 = *(const float4*)&As[k][n0];
            float4 aa1 = *(const float4*)&As[k][n0 + 4];
            float4 bb0 = *(const float4*)&Bs[k][t0];
            float4 bb1 = *(const float4*)&Bs[k][t0 + 4];
            float a[8] = {aa0.x, aa0.y, aa0.z, aa0.w, aa1.x, aa1.y, aa1.z, aa1.w};
            float b[8] = {bb0.x, bb0.y, bb0.z, bb0.w, bb1.x, bb1.y, bb1.z, bb1.w};
            #pragma unroll
            for (int i = 0; i < 8; i++)
                #pragma unroll
                for (int j = 0; j < 8; j++)
                    av[i][j] = fmaf(a[i], b[j], av[i][j]);
        }
        __syncthreads();
    }

    // Epilogue: store rst, fused projection dots
    float d1 = 0.f, d2 = 0.f;
    #pragma unroll
    for (int i = 0; i < 8; i++) {
        size_t base = (size_t)(n0 + i) * 64 + t0;
        float4 l0 = *(const float4*)(lastb + base);
        float4 l1 = *(const float4*)(lastb + base + 4);
        d1 += av[i][0] * l0.x + av[i][1] * l0.y + av[i][2] * l0.z + av[i][3] * l0.w
            + av[i][4] * l1.x + av[i][5] * l1.y + av[i][6] * l1.z + av[i][7] * l1.w;
        if (secb) {
            float4 s0 = *(const float4*)(secb + base);
            float4 s1 = *(const float4*)(secb + base + 4);
            d2 += av[i][0] * s0.x + av[i][1] * s0.y + av[i][2] * s0.z + av[i][3] * s0.w
                + av[i][4] * s1.x + av[i][5] * s1.y + av[i][6] * s1.z + av[i][7] * s1.w;
        }
        float4 o0 = {av[i][0], av[i][1], av[i][2], av[i][3]};
        float4 o1 = {av[i][4], av[i][5], av[i][6], av[i][7]};
        *(float4*)(dst + base) = o0;
        *(float4*)(dst + base + 4) = o1;
    }
    d1 = block_sum(d1, red);
    d2 = secb ? block_sum(d2, red) : 0.f;

    // Pass 2: subtract projections, accumulate norm
    float nrm = 0.f;
    float4* d4 = (float4*)dst;
    const float4* l4 = (const float4*)lastb;
    const float4* s4 = (const float4*)secb;
    for (int i = tid; i < SLICE / 4; i += NTHREADS) {
        float4 v = d4[i];
        float4 l = l4[i];
        v.x -= d1 * l.x; v.y -= d1 * l.y; v.z -= d1 * l.z; v.w -= d1 * l.w;
        if (secb) {
            float4 s = s4[i];
            v.x -= d2 * s.x; v.y -= d2 * s.y; v.z -= d2 * s.z; v.w -= d2 * s.w;
        }
        d4[i] = v;
        nrm += v.x * v.x + v.y * v.y + v.z * v.z + v.w * v.w;
    }
    nrm = block_sum(nrm, red);
    float inv = 1.f / fmaxf(sqrtf(nrm), 1e-8f);

    // Pass 3: normalize in place, accumulate into acc
    float4* a4 = (float4*)acc;
    for (int i = tid; i < SLICE / 4; i += NTHREADS) {
        float4 v = d4[i];
        v.x *= inv; v.y *= inv; v.z *= inv; v.w *= inv;
        d4[i] = v;
        float4 a = a4[i];
        a.x = fmaf(th, v.x, a.x); a.y = fmaf(th, v.y, a.y);
        a.z = fmaf(th, v.z, a.z); a.w = fmaf(th, v.w, a.w);
        a4[i] = a;
    }
    __syncthreads();
}

// ---------------- main kernel: one CTA per (b,f) slice ----------------
__global__ __launch_bounds__(NTHREADS, 1)
void st_main_kernel(const float* __restrict__ x,
                    const float* __restrict__ Ls,
                    const float* __restrict__ Lt,
                    const float* __restrict__ STE,
                    const float* __restrict__ w_t1, const float* __restrict__ b_t1,
                    const float* __restrict__ w_t2, const float* __restrict__ b_t2)
{
    __shared__ __align__(16) float As[16][512];
    __shared__ __align__(16) float Bs[16][64];
    __shared__ float red[32];
    __shared__ float theta_sm[66];
    __shared__ float h1_sm[60];

    const int tid = threadIdx.x;
    const int slice = blockIdx.x;
    const int b = slice >> 4;
    const float* xs = x + (size_t)slice * SLICE;
    float* acc = g_acc + (size_t)slice * SLICE;
    float* bufp[5];
    #pragma unroll
    for (int i = 0; i < 5; i++) bufp[i] = g_bufs + ((size_t)slice * 5 + i) * SLICE;

    // ---- theta (tiny MLP on STE), redundantly per block ----
    if (tid < 60) {
        int o = tid / 10, s = tid % 10;
        float h = b_t1[o];
        #pragma unroll
        for (int t = 0; t < 5; t++) h = fmaf(w_t1[o * 5 + t], STE[b * 50 + t * 10 + s], h);
        h1_sm[o * 10 + s] = h;
    }
    __syncthreads();
    if (tid < 66) {
        int p = tid % 11, o = tid / 11;
        float h = b_t2[p];
        #pragma unroll
        for (int s = 0; s < 10; s++) h = fmaf(w_t2[p * 10 + s], h1_sm[o * 10 + s], h);
        theta_sm[o * 11 + p] = fmaxf(h, 0.f);   // flat r = o*11 + p pairs with M order
    }

    // ---- m00 = x / fro(x);  acc = theta[0] * m00 ----
    float nv = 0.f;
    const float4* x4 = (const float4*)xs;
    for (int i = tid; i < SLICE / 4; i += NTHREADS) {
        float4 v = x4[i];
        nv += v.x * v.x + v.y * v.y + v.z * v.z + v.w * v.w;
    }
    nv = block_sum(nv, red);             // also makes theta_sm visible
    float inv = 1.f / fmaxf(sqrtf(nv), 1e-8f);
    float th0 = theta_sm[0];
    float4* b04 = (float4*)bufp[0];
    float4* a4 = (float4*)acc;
    for (int i = tid; i < SLICE / 4; i += NTHREADS) {
        float4 v = x4[i];
        v.x *= inv; v.y *= inv; v.z *= inv; v.w *= inv;
        b04[i] = v;
        float4 a = {th0 * v.x, th0 * v.y, th0 * v.z, th0 * v.w};
        a4[i] = a;
    }
    __syncthreads();

    // ---- recurrence ----
    int last_s = 0, sec_s = -1, last_t = 0, sec_t = -1;
    int r = 1;
    for (int i = 0; i <= 10; i++) {
        if (i > 0) {
            int nb = 0;
            while (nb == last_s || nb == sec_s || nb == last_t || nb == sec_t) nb++;
            basis_step(Ls, 512, 512, bufp[last_s], bufp[nb],
                       bufp[last_s], (sec_s >= 0) ? bufp[sec_s] : nullptr,
                       theta_sm[r], acc, As, Bs, red);
            sec_s = last_s; last_s = nb;
            last_t = nb; sec_t = -1;
            r++;
        }
        for (int j = 0; j < 5; j++) {
            int nb = 0;
            while (nb == last_s || nb == sec_s || nb == last_t || nb == sec_t) nb++;
            basis_step(bufp[last_t], 64, 64, Lt, bufp[nb],
                       bufp[last_t], (sec_t >= 0) ? bufp[sec_t] : nullptr,
                       theta_sm[r], acc, As, Bs, red);
            sec_t = last_t; last_t = nb;
            r++;
        }
    }
}

// ---------------- output MLP + folded BatchNorm ----------------
__global__ __launch_bounds__(256)
void st_out_kernel(const float* __restrict__ x,
                   const float* __restrict__ w_mlp, const float* __restrict__ b_mlp,
                   const float* __restrict__ gamma, const float* __restrict__ beta,
                   const float* __restrict__ mean, const float* __restrict__ var,
                   float* __restrict__ out)
{
    __shared__ float ws[64][32];
    __shared__ float bs[64];
    const int tid = threadIdx.x;
    for (int i = tid; i < 64 * 32; i += 256) {
        int o = i >> 5;
        float invs = gamma[o] * rsqrtf(var[o] + 1e-5f);
        ws[o][i & 31] = w_mlp[i] * invs;
    }
    if (tid < 64) {
        float invs = gamma[tid] * rsqrtf(var[tid] + 1e-5f);
        bs[tid] = b_mlp[tid] * invs + beta[tid] - mean[tid] * invs;
    }
    __syncthreads();

    const int b = blockIdx.y;
    const int pt = blockIdx.x * 256 + tid;   // 0..32767

    float xv[16], av[16];
    #pragma unroll
    for (int c = 0; c < 16; c++) {
        xv[c] = x[((size_t)(b * 16 + c)) * SLICE + pt];
        av[c] = g_acc[((size_t)(b * 16 + c)) * SLICE + pt];
    }
    #pragma unroll
    for (int o = 0; o < 64; o++) {
        float s = bs[o];
        #pragma unroll
        for (int c = 0; c < 16; c++) {
            s = fmaf(ws[o][c], xv[c], s);
            s = fmaf(ws[o][16 + c], av[c], s);
        }
        out[((size_t)(b * 64 + o)) * SLICE + pt] = s;
    }
}

extern "C" void kernel_launch(void* const* d_in, const int* in_sizes, int n_in,
                              void* d_out, int out_size) {
    const float* x    = (const float*)d_in[0];
    const float* Ls   = (const float*)d_in[1];
    const float* Lt   = (const float*)d_in[2];
    const float* STE  = (const float*)d_in[3];
    const float* w_t1 = (const float*)d_in[4];
    const float* b_t1 = (const float*)d_in[5];
    const float* w_t2 = (const float*)d_in[6];
    const float* b_t2 = (const float*)d_in[7];
    const float* w_mlp = (const float*)d_in[8];
    const float* b_mlp = (const float*)d_in[9];
    const float* gamma = (const float*)d_in[10];
    const float* beta  = (const float*)d_in[11];
    const float* mean  = (const float*)d_in[12];
    const float* var   = (const float*)d_in[13];
    float* out = (float*)d_out;

    st_main_kernel<<<NSLICES, NTHREADS>>>(x, Ls, Lt, STE, w_t1, b_t1, w_t2, b_t2);
    st_out_kernel<<<dim3(128, 4), 256>>>(x, w_mlp, b_mlp, gamma, beta, mean, var, out);
}

// round 3
// speedup vs baseline: 1.6302x; 1.6302x over previous
#include <cuda_runtime.h>
#include <math.h>
#include <stdint.h>

#define SLICE 32768      // 512*64 floats per (b,f) slice
#define HALF  16384      // per-rank half of a slice
#define M_HALF 256
#define NTHREADS 512
#define NSLICES 64       // B*C = 4*16

// Scratch: 5 rotation buffers + accumulator per slice (static device memory)
__device__ float g_bufs[(size_t)NSLICES * 5 * SLICE];
__device__ float g_acc[(size_t)NSLICES * SLICE];

#define CLUSTER_SYNC() do { \
    asm volatile("barrier.cluster.arrive.aligned;" ::: "memory"); \
    asm volatile("barrier.cluster.wait.aligned;" ::: "memory"); \
} while (0)

__device__ __forceinline__ uint32_t smem_u32(const void* p) {
    uint32_t a;
    asm("{ .reg .u64 t; cvta.to.shared.u64 t, %1; cvt.u32.u64 %0, t; }" : "=r"(a) : "l"(p));
    return a;
}

__device__ __forceinline__ float dsmem_peer_f32(uint32_t smem_addr, uint32_t peer) {
    uint32_t ra;
    asm volatile("mapa.shared::cluster.u32 %0, %1, %2;" : "=r"(ra) : "r"(smem_addr), "r"(peer));
    float v;
    asm volatile("ld.shared::cluster.f32 %0, [%1];" : "=f"(v) : "r"(ra));
    return v;
}

// ---------------- block reduction ----------------
__device__ __forceinline__ float block_sum(float v, float* red) {
    #pragma unroll
    for (int o = 16; o; o >>= 1) v += __shfl_xor_sync(0xffffffffu, v, o);
    int w = threadIdx.x >> 5, l = threadIdx.x & 31;
    if (l == 0) red[w] = v;
    __syncthreads();
    if (w == 0) {
        float t = (l < 16) ? red[l] : 0.f;
        #pragma unroll
        for (int o = 8; o; o >>= 1) t += __shfl_xor_sync(0xffffffffu, t, o);
        if (l == 0) red[0] = t;
    }
    __syncthreads();
    float r = red[0];
    __syncthreads();
    return r;
}

// ---------------- one basis step (per-rank half of the M dimension) ----------------
// rst = A @ Bm  (my M_HALF rows); d1=<rst,last>, d2=<rst,sec> (global via DSMEM);
// dst = (rst - d1*last - d2*sec) / sqrt(max(|rst|^2 - d1^2 - d2^2, 0));  acc += th*dst.
// A: [M_HALF, K] row-major (lda); Bm: [K, 64] contiguous (peer-written iff spatialB).
__device__ void basis_step(const float* __restrict__ A, int lda, int K, bool spatialB,
                           const float* __restrict__ Bm,
                           float* __restrict__ dsth,
                           const float* __restrict__ lasth,
                           const float* __restrict__ sech,
                           float th, float* __restrict__ acch,
                           float (*As)[M_HALF], float (*Bs)[64], float* red,
                           float* xch, uint32_t xch_addr, uint32_t peer)
{
    const int tid = threadIdx.x;
    const int rl  = tid >> 1;          // 0..255 staging row
    const int kh  = (tid & 1) * 8;     // which 8 of the 16 k's this thread stages
    const int n0  = (tid >> 3) * 4;    // 4-row group
    const int t0  = (tid & 7) * 8;     // 8-col group
    const bool has_sec = (sech != nullptr);

    float av[4][8];
    #pragma unroll
    for (int i = 0; i < 4; i++)
        #pragma unroll
        for (int j = 0; j < 8; j++) av[i][j] = 0.f;

    for (int kt = 0; kt < K; kt += 16) {
        const float* ar = A + (size_t)rl * lda + kt + kh;
        float4 a0 = *(const float4*)(ar);
        float4 a1 = *(const float4*)(ar + 4);
        As[kh + 0][rl] = a0.x; As[kh + 1][rl] = a0.y; As[kh + 2][rl] = a0.z; As[kh + 3][rl] = a0.w;
        As[kh + 4][rl] = a1.x; As[kh + 5][rl] = a1.y; As[kh + 6][rl] = a1.z; As[kh + 7][rl] = a1.w;
        if (tid < 256) {
            const float4* src = (const float4*)(Bm + (size_t)kt * 64) + tid;
            float4 bv = spatialB ? __ldcg(src) : *src;  // peer-written data: bypass L1
            ((float4*)&Bs[0][0])[tid] = bv;
        }
        __syncthreads();

        #pragma unroll
        for (int k = 0; k < 16; k++) {
            float4 aa = *(const float4*)&As[k][n0];
            float4 b0 = *(const float4*)&Bs[k][t0];
            float4 b1 = *(const float4*)&Bs[k][t0 + 4];
            float a[4] = {aa.x, aa.y, aa.z, aa.w};
            float b[8] = {b0.x, b0.y, b0.z, b0.w, b1.x, b1.y, b1.z, b1.w};
            #pragma unroll
            for (int i = 0; i < 4; i++)
                #pragma unroll
                for (int j = 0; j < 8; j++)
                    av[i][j] = fmaf(a[i], b[j], av[i][j]);
        }
        __syncthreads();
    }

    // Partial dots + norm from registers (cache last tile in regs)
    float pd1 = 0.f, pd2 = 0.f, pr2 = 0.f;
    float4 lv[4][2];
    #pragma unroll
    for (int i = 0; i < 4; i++) {
        size_t base = (size_t)(n0 + i) * 64 + t0;
        lv[i][0] = *(const float4*)(lasth + base);
        lv[i][1] = *(const float4*)(lasth + base + 4);
        const float* lp = (const float*)&lv[i][0];
        #pragma unroll
        for (int j = 0; j < 8; j++) {
            pd1 = fmaf(av[i][j], lp[j], pd1);
            pr2 = fmaf(av[i][j], av[i][j], pr2);
        }
        if (has_sec) {
            float4 s0 = *(const float4*)(sech + base);
            float4 s1 = *(const float4*)(sech + base + 4);
            float s[8] = {s0.x, s0.y, s0.z, s0.w, s1.x, s1.y, s1.z, s1.w};
            #pragma unroll
            for (int j = 0; j < 8; j++) pd2 = fmaf(av[i][j], s[j], pd2);
        }
    }
    pd1 = block_sum(pd1, red);
    pd2 = has_sec ? block_sum(pd2, red) : 0.f;
    pr2 = block_sum(pr2, red);
    if (tid == 0) { xch[0] = pd1; xch[1] = pd2; xch[2] = pr2; }
    CLUSTER_SYNC();
    float d1 = pd1 + dsmem_peer_f32(xch_addr + 0, peer);
    float d2 = has_sec ? (pd2 + dsmem_peer_f32(xch_addr + 4, peer)) : 0.f;
    float r2 = pr2 + dsmem_peer_f32(xch_addr + 8, peer);
    float n2 = r2 - d1 * d1 - d2 * d2;
    float inv = 1.f / fmaxf(sqrtf(fmaxf(n2, 0.f)), 1e-8f);

    // Write normalized dst + acc update, all from registers
    #pragma unroll
    for (int i = 0; i < 4; i++) {
        size_t base = (size_t)(n0 + i) * 64 + t0;
        const float* lp = (const float*)&lv[i][0];
        float v[8];
        if (has_sec) {
            float4 s0 = *(const float4*)(sech + base);
            float4 s1 = *(const float4*)(sech + base + 4);
            float s[8] = {s0.x, s0.y, s0.z, s0.w, s1.x, s1.y, s1.z, s1.w};
            #pragma unroll
            for (int j = 0; j < 8; j++) v[j] = (av[i][j] - d1 * lp[j] - d2 * s[j]) * inv;
        } else {
            #pragma unroll
            for (int j = 0; j < 8; j++) v[j] = (av[i][j] - d1 * lp[j]) * inv;
        }
        *(float4*)(dsth + base)     = make_float4(v[0], v[1], v[2], v[3]);
        *(float4*)(dsth + base + 4) = make_float4(v[4], v[5], v[6], v[7]);
        float4 a0 = *(float4*)(acch + base);
        float4 a1 = *(float4*)(acch + base + 4);
        a0.x = fmaf(th, v[0], a0.x); a0.y = fmaf(th, v[1], a0.y);
        a0.z = fmaf(th, v[2], a0.z); a0.w = fmaf(th, v[3], a0.w);
        a1.x = fmaf(th, v[4], a1.x); a1.y = fmaf(th, v[5], a1.y);
        a1.z = fmaf(th, v[6], a1.z); a1.w = fmaf(th, v[7], a1.w);
        *(float4*)(acch + base)     = a0;
        *(float4*)(acch + base + 4) = a1;
    }
    CLUSTER_SYNC();   // dst halves visible before anyone reads them next step
}

// ---------------- main kernel: 2-CTA cluster per (b,f) slice ----------------
__global__ void __cluster_dims__(2, 1, 1) __launch_bounds__(NTHREADS, 1)
st_main_kernel(const float* __restrict__ x,
               const float* __restrict__ Ls,
               const float* __restrict__ Lt,
               const float* __restrict__ STE,
               const float* __restrict__ w_t1, const float* __restrict__ b_t1,
               const float* __restrict__ w_t2, const float* __restrict__ b_t2)
{
    __shared__ __align__(16) float As[16][M_HALF];
    __shared__ __align__(16) float Bs[16][64];
    __shared__ float red[32];
    __shared__ float theta_sm[66];
    __shared__ float h1_sm[60];
    __shared__ __align__(16) float xch[4];

    const int tid = threadIdx.x;
    const int slice = blockIdx.x >> 1;
    const uint32_t rank = blockIdx.x & 1;
    const uint32_t peer = rank ^ 1;
    const int b = slice >> 4;
    const uint32_t xch_addr = smem_u32(xch);
    const size_t hoff = (size_t)rank * HALF;

    const float* xs = x + (size_t)slice * SLICE;
    float* acc = g_acc + (size_t)slice * SLICE;
    float* bufp[5];
    #pragma unroll
    for (int i = 0; i < 5; i++) bufp[i] = g_bufs + ((size_t)slice * 5 + i) * SLICE;

    // ---- theta (tiny MLP on STE), redundantly per CTA ----
    if (tid < 60) {
        int o = tid / 10, s = tid % 10;
        float h = b_t1[o];
        #pragma unroll
        for (int t = 0; t < 5; t++) h = fmaf(w_t1[o * 5 + t], STE[b * 50 + t * 10 + s], h);
        h1_sm[o * 10 + s] = h;
    }
    __syncthreads();
    if (tid < 66) {
        int p = tid % 11, o = tid / 11;
        float h = b_t2[p];
        #pragma unroll
        for (int s = 0; s < 10; s++) h = fmaf(w_t2[p * 10 + s], h1_sm[o * 10 + s], h);
        theta_sm[o * 11 + p] = fmaxf(h, 0.f);   // flat r = o*11 + p matches M order
    }
    __syncthreads();

    // ---- m00 = x / fro(x);  acc = theta[0] * m00  (my half) ----
    float pnv = 0.f;
    const float4* x4 = (const float4*)(xs + hoff);
    for (int i = tid; i < HALF / 4; i += NTHREADS) {
        float4 v = x4[i];
        pnv += v.x * v.x + v.y * v.y + v.z * v.z + v.w * v.w;
    }
    pnv = block_sum(pnv, red);
    if (tid == 0) xch[0] = pnv;
    CLUSTER_SYNC();
    float nv = pnv + dsmem_peer_f32(xch_addr, peer);
    float inv = 1.f / fmaxf(sqrtf(nv), 1e-8f);
    float th0 = theta_sm[0];
    float4* b04 = (float4*)(bufp[0] + hoff);
    float4* a4 = (float4*)(acc + hoff);
    for (int i = tid; i < HALF / 4; i += NTHREADS) {
        float4 v = x4[i];
        v.x *= inv; v.y *= inv; v.z *= inv; v.w *= inv;
        b04[i] = v;
        a4[i] = make_float4(th0 * v.x, th0 * v.y, th0 * v.z, th0 * v.w);
    }
    CLUSTER_SYNC();

    // ---- recurrence ----
    int last_s = 0, sec_s = -1, last_t = 0, sec_t = -1;
    int r = 1;
    for (int i = 0; i <= 10; i++) {
        if (i > 0) {
            int nb = 0;
            while (nb == last_s || nb == sec_s || nb == last_t || nb == sec_t) nb++;
            // spatial: A = my rows of Ls [256 x 512]; B = full last buffer
            basis_step(Ls + (size_t)rank * M_HALF * 512, 512, 512, true,
                       bufp[last_s],
                       bufp[nb] + hoff,
                       bufp[last_s] + hoff,
                       (sec_s >= 0) ? bufp[sec_s] + hoff : nullptr,
                       theta_sm[r], acc + hoff, As, Bs, red, xch, xch_addr, peer);
            sec_s = last_s; last_s = nb;
            last_t = nb; sec_t = -1;
            r++;
        }
        for (int j = 0; j < 5; j++) {
            int nb = 0;
            while (nb == last_s || nb == sec_s || nb == last_t || nb == sec_t) nb++;
            // temporal: A = my half of last [256 x 64]; B = Lt
            basis_step(bufp[last_t] + hoff, 64, 64, false,
                       Lt,
                       bufp[nb] + hoff,
                       bufp[last_t] + hoff,
                       (sec_t >= 0) ? bufp[sec_t] + hoff : nullptr,
                       theta_sm[r], acc + hoff, As, Bs, red, xch, xch_addr, peer);
            sec_t = last_t; last_t = nb;
            r++;
        }
    }
}

// ---------------- output MLP + folded BatchNorm ----------------
__global__ __launch_bounds__(256)
void st_out_kernel(const float* __restrict__ x,
                   const float* __restrict__ w_mlp, const float* __restrict__ b_mlp,
                   const float* __restrict__ gamma, const float* __restrict__ beta,
                   const float* __restrict__ mean, const float* __restrict__ var,
                   float* __restrict__ out)
{
    __shared__ float ws[64][32];
    __shared__ float bs[64];
    const int tid = threadIdx.x;
    for (int i = tid; i < 64 * 32; i += 256) {
        int o = i >> 5;
        float invs = gamma[o] * rsqrtf(var[o] + 1e-5f);
        ws[o][i & 31] = w_mlp[i] * invs;
    }
    if (tid < 64) {
        float invs = gamma[tid] * rsqrtf(var[tid] + 1e-5f);
        bs[tid] = b_mlp[tid] * invs + beta[tid] - mean[tid] * invs;
    }
    __syncthreads();

    const int b = blockIdx.y;
    const int pt = blockIdx.x * 256 + tid;   // 0..32767

    float xv[16], av[16];
    #pragma unroll
    for (int c = 0; c < 16; c++) {
        xv[c] = x[((size_t)(b * 16 + c)) * SLICE + pt];
        av[c] = g_acc[((size_t)(b * 16 + c)) * SLICE + pt];
    }
    #pragma unroll
    for (int o = 0; o < 64; o++) {
        float s = bs[o];
        #pragma unroll
        for (int c = 0; c < 16; c++) {
            s = fmaf(ws[o][c], xv[c], s);
            s = fmaf(ws[o][16 + c], av[c], s);
        }
        out[((size_t)(b * 64 + o)) * SLICE + pt] = s;
    }
}

extern "C" void kernel_launch(void* const* d_in, const int* in_sizes, int n_in,
                              void* d_out, int out_size) {
    const float* x    = (const float*)d_in[0];
    const float* Ls   = (const float*)d_in[1];
    const float* Lt   = (const float*)d_in[2];
    const float* STE  = (const float*)d_in[3];
    const float* w_t1 = (const float*)d_in[4];
    const float* b_t1 = (const float*)d_in[5];
    const float* w_t2 = (const float*)d_in[6];
    const float* b_t2 = (const float*)d_in[7];
    const float* w_mlp = (const float*)d_in[8];
    const float* b_mlp = (const float*)d_in[9];
    const float* gamma = (const float*)d_in[10];
    const float* beta  = (const float*)d_in[11];
    const float* mean  = (const float*)d_in[12];
    const float* var   = (const float*)d_in[13];
    float* out = (float*)d_out;

    st_main_kernel<<<NSLICES * 2, NTHREADS>>>(x, Ls, Lt, STE, w_t1, b_t1, w_t2, b_t2);
    st_out_kernel<<<dim3(128, 4), 256>>>(x, w_mlp, b_mlp, gamma, beta, mean, var, out);
}

// round 4
// speedup vs baseline: 1.7266x; 1.0592x over previous
#include <cuda_runtime.h>
#include <math.h>
#include <stdint.h>

#define SLICE 32768      // 512*64 floats per (b,f) slice
#define HALF  16384      // per-rank half of a slice
#define M_HALF 256
#define NTHREADS 512
#define NSLICES 64       // B*C = 4*16

__device__ float g_bufs[(size_t)NSLICES * 5 * SLICE];
__device__ float g_acc[(size_t)NSLICES * SLICE];

#define CLUSTER_SYNC() do { \
    asm volatile("barrier.cluster.arrive.aligned;" ::: "memory"); \
    asm volatile("barrier.cluster.wait.aligned;" ::: "memory"); \
} while (0)

__device__ __forceinline__ uint32_t smem_u32(const void* p) {
    uint32_t a;
    asm("{ .reg .u64 t; cvta.to.shared.u64 t, %1; cvt.u32.u64 %0, t; }" : "=r"(a) : "l"(p));
    return a;
}

__device__ __forceinline__ float dsmem_peer_f32(uint32_t smem_addr, uint32_t peer) {
    uint32_t ra;
    asm volatile("mapa.shared::cluster.u32 %0, %1, %2;" : "=r"(ra) : "r"(smem_addr), "r"(peer));
    float v;
    asm volatile("ld.shared::cluster.f32 %0, [%1];" : "=f"(v) : "r"(ra));
    return v;
}

// ---------------- fused 3-value block reduction ----------------
__device__ __forceinline__ void block_sum3(float& a, float& b, float& c, float (*red)[32]) {
    #pragma unroll
    for (int o = 16; o; o >>= 1) {
        a += __shfl_xor_sync(0xffffffffu, a, o);
        b += __shfl_xor_sync(0xffffffffu, b, o);
        c += __shfl_xor_sync(0xffffffffu, c, o);
    }
    int w = threadIdx.x >> 5, l = threadIdx.x & 31;
    if (l == 0) { red[0][w] = a; red[1][w] = b; red[2][w] = c; }
    __syncthreads();
    if (w == 0) {
        float ta = (l < 16) ? red[0][l] : 0.f;
        float tb = (l < 16) ? red[1][l] : 0.f;
        float tc = (l < 16) ? red[2][l] : 0.f;
        #pragma unroll
        for (int o = 8; o; o >>= 1) {
            ta += __shfl_xor_sync(0xffffffffu, ta, o);
            tb += __shfl_xor_sync(0xffffffffu, tb, o);
            tc += __shfl_xor_sync(0xffffffffu, tc, o);
        }
        if (l == 0) { red[0][0] = ta; red[1][0] = tb; red[2][0] = tc; }
    }
    __syncthreads();
    a = red[0][0]; b = red[1][0]; c = red[2][0];
    __syncthreads();
}

// ---------------- one basis step (per-rank half of the M dimension) ----------------
// rst = A @ Bm (my 256 rows); analytic-norm Gram-Schmidt epilogue; acc += th*dst.
template<bool SPATIAL>
__device__ void basis_step(const float* __restrict__ A,
                           const float* __restrict__ Bm,
                           float* __restrict__ dsth,
                           const float* __restrict__ lasth,
                           const float* __restrict__ sech,
                           float th, float* __restrict__ acch,
                           float (*As)[16][M_HALF], float (*Bs)[16][64],
                           float (*red)[32],
                           float* xch, uint32_t xch_addr, uint32_t peer,
                           int phase, bool trail)
{
    constexpr int K   = SPATIAL ? 512 : 64;
    constexpr int LDA = SPATIAL ? 512 : 64;
    constexpr int TILES = K / 16;

    const int tid = threadIdx.x;
    const int rl  = tid >> 1;          // staging row 0..255
    const int kh  = (tid & 1) * 8;     // which 8 of 16 k's this thread stages
    const int n0  = (tid >> 3) * 4;    // 4-row group
    const int t0  = (tid & 7) * 8;     // 8-col group
    const bool has_sec = (sech != nullptr);

    float av[4][8];
    #pragma unroll
    for (int i = 0; i < 4; i++)
        #pragma unroll
        for (int j = 0; j < 8; j++) av[i][j] = 0.f;

    // ---- prologue: stage tile 0 ----
    float4 pa0, pa1, pbv;
    {
        const float* ar = A + (size_t)rl * LDA + kh;
        pa0 = *(const float4*)(ar);
        pa1 = *(const float4*)(ar + 4);
        if (tid < 256) {
            const float4* src = (const float4*)Bm + tid;
            pbv = SPATIAL ? __ldcg(src) : *src;
        }
    }
    {
        As[0][kh + 0][rl] = pa0.x; As[0][kh + 1][rl] = pa0.y;
        As[0][kh + 2][rl] = pa0.z; As[0][kh + 3][rl] = pa0.w;
        As[0][kh + 4][rl] = pa1.x; As[0][kh + 5][rl] = pa1.y;
        As[0][kh + 6][rl] = pa1.z; As[0][kh + 7][rl] = pa1.w;
        if (tid < 256) ((float4*)&Bs[0][0][0])[tid] = pbv;
    }
    __syncthreads();

    int p = 0;
    for (int t = 0; t < TILES; t++) {
        // prefetch next tile into registers (overlaps compute)
        float4 na0, na1, nbv;
        const bool more = (t + 1 < TILES);
        if (more) {
            const int kt = (t + 1) * 16;
            const float* ar = A + (size_t)rl * LDA + kt + kh;
            na0 = *(const float4*)(ar);
            na1 = *(const float4*)(ar + 4);
            if (tid < 256) {
                const float4* src = (const float4*)(Bm + (size_t)kt * 64) + tid;
                nbv = SPATIAL ? __ldcg(src) : *src;
            }
        }

        #pragma unroll
        for (int k = 0; k < 16; k++) {
            float4 aa = *(const float4*)&As[p][k][n0];
            float4 b0 = *(const float4*)&Bs[p][k][t0];
            float4 b1 = *(const float4*)&Bs[p][k][t0 + 4];
            float a[4] = {aa.x, aa.y, aa.z, aa.w};
            float b[8] = {b0.x, b0.y, b0.z, b0.w, b1.x, b1.y, b1.z, b1.w};
            #pragma unroll
            for (int i = 0; i < 4; i++)
                #pragma unroll
                for (int j = 0; j < 8; j++)
                    av[i][j] = fmaf(a[i], b[j], av[i][j]);
        }

        if (more) {
            const int q = p ^ 1;       // writes to other buffer: no race with readers of p
            As[q][kh + 0][rl] = na0.x; As[q][kh + 1][rl] = na0.y;
            As[q][kh + 2][rl] = na0.z; As[q][kh + 3][rl] = na0.w;
            As[q][kh + 4][rl] = na1.x; As[q][kh + 5][rl] = na1.y;
            As[q][kh + 6][rl] = na1.z; As[q][kh + 7][rl] = na1.w;
            if (tid < 256) ((float4*)&Bs[q][0][0])[tid] = nbv;
            __syncthreads();
            p = q;
        }
    }

    // ---- epilogue: partial dots + norm from registers ----
    float pd1 = 0.f, pd2 = 0.f, pr2 = 0.f;
    float4 lv[4][2];
    #pragma unroll
    for (int i = 0; i < 4; i++) {
        size_t base = (size_t)(n0 + i) * 64 + t0;
        lv[i][0] = *(const float4*)(lasth + base);
        lv[i][1] = *(const float4*)(lasth + base + 4);
        const float* lp = (const float*)&lv[i][0];
        #pragma unroll
        for (int j = 0; j < 8; j++) {
            pd1 = fmaf(av[i][j], lp[j], pd1);
            pr2 = fmaf(av[i][j], av[i][j], pr2);
        }
        if (has_sec) {
            float4 s0 = *(const float4*)(sech + base);
            float4 s1 = *(const float4*)(sech + base + 4);
            float s[8] = {s0.x, s0.y, s0.z, s0.w, s1.x, s1.y, s1.z, s1.w};
            #pragma unroll
            for (int j = 0; j < 8; j++) pd2 = fmaf(av[i][j], s[j], pd2);
        }
    }
    block_sum3(pd1, pd2, pr2, red);

    const int xb = phase * 4;
    if (tid == 0) { xch[xb + 0] = pd1; xch[xb + 1] = pd2; xch[xb + 2] = pr2; }
    CLUSTER_SYNC();
    float d1 = pd1 + dsmem_peer_f32(xch_addr + 4 * xb + 0, peer);
    float d2 = has_sec ? (pd2 + dsmem_peer_f32(xch_addr + 4 * xb + 4, peer)) : 0.f;
    float r2 = pr2 + dsmem_peer_f32(xch_addr + 4 * xb + 8, peer);
    float n2 = r2 - d1 * d1 - d2 * d2;
    float inv = 1.f / fmaxf(sqrtf(fmaxf(n2, 0.f)), 1e-8f);

    // ---- write normalized dst + acc update from registers ----
    #pragma unroll
    for (int i = 0; i < 4; i++) {
        size_t base = (size_t)(n0 + i) * 64 + t0;
        const float* lp = (const float*)&lv[i][0];
        float v[8];
        if (has_sec) {
            float4 s0 = *(const float4*)(sech + base);
            float4 s1 = *(const float4*)(sech + base + 4);
            float s[8] = {s0.x, s0.y, s0.z, s0.w, s1.x, s1.y, s1.z, s1.w};
            #pragma unroll
            for (int j = 0; j < 8; j++) v[j] = (av[i][j] - d1 * lp[j] - d2 * s[j]) * inv;
        } else {
            #pragma unroll
            for (int j = 0; j < 8; j++) v[j] = (av[i][j] - d1 * lp[j]) * inv;
        }
        *(float4*)(dsth + base)     = make_float4(v[0], v[1], v[2], v[3]);
        *(float4*)(dsth + base + 4) = make_float4(v[4], v[5], v[6], v[7]);
        float4 a0 = *(float4*)(acch + base);
        float4 a1 = *(float4*)(acch + base + 4);
        a0.x = fmaf(th, v[0], a0.x); a0.y = fmaf(th, v[1], a0.y);
        a0.z = fmaf(th, v[2], a0.z); a0.w = fmaf(th, v[3], a0.w);
        a1.x = fmaf(th, v[4], a1.x); a1.y = fmaf(th, v[5], a1.y);
        a1.z = fmaf(th, v[6], a1.z); a1.w = fmaf(th, v[7], a1.w);
        *(float4*)(acch + base)     = a0;
        *(float4*)(acch + base + 4) = a1;
    }
    if (trail) CLUSTER_SYNC();   // dst visibility to peer — only before spatial steps
}

// ---------------- main kernel: 2-CTA cluster per (b,f) slice ----------------
__global__ void __cluster_dims__(2, 1, 1) __launch_bounds__(NTHREADS, 1)
st_main_kernel(const float* __restrict__ x,
               const float* __restrict__ Ls,
               const float* __restrict__ Lt,
               const float* __restrict__ STE,
               const float* __restrict__ w_t1, const float* __restrict__ b_t1,
               const float* __restrict__ w_t2, const float* __restrict__ b_t2)
{
    __shared__ __align__(16) float As[2][16][M_HALF];
    __shared__ __align__(16) float Bs[2][16][64];
    __shared__ float red[3][32];
    __shared__ float theta_sm[66];
    __shared__ float h1_sm[60];
    __shared__ __align__(16) float xch[8];

    const int tid = threadIdx.x;
    const int slice = blockIdx.x >> 1;
    const uint32_t rank = blockIdx.x & 1;
    const uint32_t peer = rank ^ 1;
    const int b = slice >> 4;
    const uint32_t xch_addr = smem_u32(xch);
    const size_t hoff = (size_t)rank * HALF;

    const float* xs = x + (size_t)slice * SLICE;
    float* acc = g_acc + (size_t)slice * SLICE;
    float* bufp[5];
    #pragma unroll
    for (int i = 0; i < 5; i++) bufp[i] = g_bufs + ((size_t)slice * 5 + i) * SLICE;

    // ---- theta (tiny MLP on STE), redundantly per CTA ----
    if (tid < 60) {
        int o = tid / 10, s = tid % 10;
        float h = b_t1[o];
        #pragma unroll
        for (int t = 0; t < 5; t++) h = fmaf(w_t1[o * 5 + t], STE[b * 50 + t * 10 + s], h);
        h1_sm[o * 10 + s] = h;
    }
    __syncthreads();
    if (tid < 66) {
        int p = tid % 11, o = tid / 11;
        float h = b_t2[p];
        #pragma unroll
        for (int s = 0; s < 10; s++) h = fmaf(w_t2[p * 10 + s], h1_sm[o * 10 + s], h);
        theta_sm[o * 11 + p] = fmaxf(h, 0.f);   // flat r = o*11 + p matches M order
    }
    __syncthreads();

    // ---- m00 = x / fro(x);  acc = theta[0] * m00  (my half) ----
    float pnv = 0.f, z1 = 0.f, z2 = 0.f;
    const float4* x4 = (const float4*)(xs + hoff);
    for (int i = tid; i < HALF / 4; i += NTHREADS) {
        float4 v = x4[i];
        pnv += v.x * v.x + v.y * v.y + v.z * v.z + v.w * v.w;
    }
    block_sum3(pnv, z1, z2, red);
    if (tid == 0) xch[3] = pnv;
    CLUSTER_SYNC();
    float nv = pnv + dsmem_peer_f32(xch_addr + 12, peer);
    float inv = 1.f / fmaxf(sqrtf(nv), 1e-8f);
    float th0 = theta_sm[0];
    float4* b04 = (float4*)(bufp[0] + hoff);
    float4* a4 = (float4*)(acc + hoff);
    for (int i = tid; i < HALF / 4; i += NTHREADS) {
        float4 v = x4[i];
        v.x *= inv; v.y *= inv; v.z *= inv; v.w *= inv;
        b04[i] = v;
        a4[i] = make_float4(th0 * v.x, th0 * v.y, th0 * v.z, th0 * v.w);
    }
    __syncthreads();   // bufp[0] half complete before step 1 (temporal, own-half only)

    // ---- recurrence ----
    int last_s = 0, sec_s = -1, last_t = 0, sec_t = -1;
    int r = 1;
    for (int i = 0; i <= 10; i++) {
        if (i > 0) {
            int nb = 0;
            while (nb == last_s || nb == sec_s || nb == last_t || nb == sec_t) nb++;
            bool trail = (r % 6 == 5) && (r <= 59);
            basis_step<true>(Ls + (size_t)rank * M_HALF * 512,
                             bufp[last_s],
                             bufp[nb] + hoff,
                             bufp[last_s] + hoff,
                             (sec_s >= 0) ? bufp[sec_s] + hoff : nullptr,
                             theta_sm[r], acc + hoff, As, Bs, red,
                             xch, xch_addr, peer, r & 1, trail);
            sec_s = last_s; last_s = nb;
            last_t = nb; sec_t = -1;
            r++;
        }
        for (int j = 0; j < 5; j++) {
            int nb = 0;
            while (nb == last_s || nb == sec_s || nb == last_t || nb == sec_t) nb++;
            bool trail = (r % 6 == 5) && (r <= 59);
            basis_step<false>(bufp[last_t] + hoff,
                              Lt,
                              bufp[nb] + hoff,
                              bufp[last_t] + hoff,
                              (sec_t >= 0) ? bufp[sec_t] + hoff : nullptr,
                              theta_sm[r], acc + hoff, As, Bs, red,
                              xch, xch_addr, peer, r & 1, trail);
            sec_t = last_t; last_t = nb;
            r++;
        }
    }
}

// ---------------- output MLP + folded BatchNorm ----------------
__global__ __launch_bounds__(256)
void st_out_kernel(const float* __restrict__ x,
                   const float* __restrict__ w_mlp, const float* __restrict__ b_mlp,
                   const float* __restrict__ gamma, const float* __restrict__ beta,
                   const float* __restrict__ mean, const float* __restrict__ var,
                   float* __restrict__ out)
{
    __shared__ float ws[64][32];
    __shared__ float bs[64];
    const int tid = threadIdx.x;
    for (int i = tid; i < 64 * 32; i += 256) {
        int o = i >> 5;
        float invs = gamma[o] * rsqrtf(var[o] + 1e-5f);
        ws[o][i & 31] = w_mlp[i] * invs;
    }
    if (tid < 64) {
        float invs = gamma[tid] * rsqrtf(var[tid] + 1e-5f);
        bs[tid] = b_mlp[tid] * invs + beta[tid] - mean[tid] * invs;
    }
    __syncthreads();

    const int b = blockIdx.y;
    const int pt = blockIdx.x * 256 + tid;   // 0..32767

    float xv[16], av[16];
    #pragma unroll
    for (int c = 0; c < 16; c++) {
        xv[c] = x[((size_t)(b * 16 + c)) * SLICE + pt];
        av[c] = g_acc[((size_t)(b * 16 + c)) * SLICE + pt];
    }
    #pragma unroll
    for (int o = 0; o < 64; o++) {
        float s = bs[o];
        #pragma unroll
        for (int c = 0; c < 16; c++) {
            s = fmaf(ws[o][c], xv[c], s);
            s = fmaf(ws[o][16 + c], av[c], s);
        }
        out[((size_t)(b * 64 + o)) * SLICE + pt] = s;
    }
}

extern "C" void kernel_launch(void* const* d_in, const int* in_sizes, int n_in,
                              void* d_out, int out_size) {
    const float* x    = (const float*)d_in[0];
    const float* Ls   = (const float*)d_in[1];
    const float* Lt   = (const float*)d_in[2];
    const float* STE  = (const float*)d_in[3];
    const float* w_t1 = (const float*)d_in[4];
    const float* b_t1 = (const float*)d_in[5];
    const float* w_t2 = (const float*)d_in[6];
    const float* b_t2 = (const float*)d_in[7];
    const float* w_mlp = (const float*)d_in[8];
    const float* b_mlp = (const float*)d_in[9];
    const float* gamma = (const float*)d_in[10];
    const float* beta  = (const float*)d_in[11];
    const float* mean  = (const float*)d_in[12];
    const float* var   = (const float*)d_in[13];
    float* out = (float*)d_out;

    st_main_kernel<<<NSLICES * 2, NTHREADS>>>(x, Ls, Lt, STE, w_t1, b_t1, w_t2, b_t2);
    st_out_kernel<<<dim3(128, 4), 256>>>(x, w_mlp, b_mlp, gamma, beta, mean, var, out);
}

// round 5
// speedup vs baseline: 1.7277x; 1.0006x over previous
#include <cuda_runtime.h>
#include <math.h>
#include <stdint.h>

#define SLICE 32768      // 512*64 floats per (b,f) slice
#define HALF  16384      // per-rank half of a slice
#define M_HALF 256
#define NTHREADS 512
#define NSLICES 64       // B*C = 4*16

__device__ float g_bufs[(size_t)NSLICES * 5 * SLICE];
__device__ float g_acc[(size_t)NSLICES * SLICE];

#define CLUSTER_SYNC() do { \
    asm volatile("barrier.cluster.arrive.aligned;" ::: "memory"); \
    asm volatile("barrier.cluster.wait.aligned;" ::: "memory"); \
} while (0)

__device__ __forceinline__ uint32_t smem_u32(const void* p) {
    uint32_t a;
    asm("{ .reg .u64 t; cvta.to.shared.u64 t, %1; cvt.u32.u64 %0, t; }" : "=r"(a) : "l"(p));
    return a;
}

__device__ __forceinline__ float dsmem_peer_f32(uint32_t smem_addr, uint32_t peer) {
    uint32_t ra;
    asm volatile("mapa.shared::cluster.u32 %0, %1, %2;" : "=r"(ra) : "r"(smem_addr), "r"(peer));
    float v;
    asm volatile("ld.shared::cluster.f32 %0, [%1];" : "=f"(v) : "r"(ra));
    return v;
}

// ---------------- fused 3-value block reduction ----------------
__device__ __forceinline__ void block_sum3(float& a, float& b, float& c, float (*red)[32]) {
    #pragma unroll
    for (int o = 16; o; o >>= 1) {
        a += __shfl_xor_sync(0xffffffffu, a, o);
        b += __shfl_xor_sync(0xffffffffu, b, o);
        c += __shfl_xor_sync(0xffffffffu, c, o);
    }
    int w = threadIdx.x >> 5, l = threadIdx.x & 31;
    if (l == 0) { red[0][w] = a; red[1][w] = b; red[2][w] = c; }
    __syncthreads();
    if (w == 0) {
        float ta = (l < 16) ? red[0][l] : 0.f;
        float tb = (l < 16) ? red[1][l] : 0.f;
        float tc = (l < 16) ? red[2][l] : 0.f;
        #pragma unroll
        for (int o = 8; o; o >>= 1) {
            ta += __shfl_xor_sync(0xffffffffu, ta, o);
            tb += __shfl_xor_sync(0xffffffffu, tb, o);
            tc += __shfl_xor_sync(0xffffffffu, tc, o);
        }
        if (l == 0) { red[0][0] = ta; red[1][0] = tb; red[2][0] = tc; }
    }
    __syncthreads();
    a = red[0][0]; b = red[1][0]; c = red[2][0];
    __syncthreads();
}

// ---------------- one basis step (per-rank half of the M dimension) ----------------
// rst = A @ Bm (my 256 rows); analytic-norm Gram-Schmidt epilogue; acc += th*dst.
template<bool SPATIAL>
__device__ void basis_step(const float* __restrict__ A,
                           const float* __restrict__ Bm,
                           float* __restrict__ dsth,
                           const float* __restrict__ lasth,
                           const float* __restrict__ sech,
                           float th, float* __restrict__ acch,
                           float (*As)[16][M_HALF], float (*Bs)[16][64],
                           float (*red)[32],
                           float* xch, uint32_t xch_addr, uint32_t peer,
                           int phase, bool trail)
{
    constexpr int K   = SPATIAL ? 512 : 64;
    constexpr int LDA = SPATIAL ? 512 : 64;
    constexpr int TILES = K / 16;

    const int tid = threadIdx.x;
    const int rl  = tid >> 1;          // staging row 0..255
    const int kh  = (tid & 1) * 8;     // which 8 of 16 k's this thread stages
    const int n0  = (tid >> 3) * 4;    // 4-row group
    const int t0  = (tid & 7) * 8;     // 8-col group
    const bool has_sec = (sech != nullptr);

    float av[4][8];
    #pragma unroll
    for (int i = 0; i < 4; i++)
        #pragma unroll
        for (int j = 0; j < 8; j++) av[i][j] = 0.f;

    // ---- prologue: stage tile 0 ----
    float4 pa0, pa1, pbv;
    {
        const float* ar = A + (size_t)rl * LDA + kh;
        pa0 = *(const float4*)(ar);
        pa1 = *(const float4*)(ar + 4);
        if (tid < 256) {
            const float4* src = (const float4*)Bm + tid;
            pbv = SPATIAL ? __ldcg(src) : *src;
        }
    }
    {
        As[0][kh + 0][rl] = pa0.x; As[0][kh + 1][rl] = pa0.y;
        As[0][kh + 2][rl] = pa0.z; As[0][kh + 3][rl] = pa0.w;
        As[0][kh + 4][rl] = pa1.x; As[0][kh + 5][rl] = pa1.y;
        As[0][kh + 6][rl] = pa1.z; As[0][kh + 7][rl] = pa1.w;
        if (tid < 256) ((float4*)&Bs[0][0][0])[tid] = pbv;
    }
    __syncthreads();

    int p = 0;
    for (int t = 0; t < TILES; t++) {
        // prefetch next tile into registers (overlaps compute)
        float4 na0, na1, nbv;
        const bool more = (t + 1 < TILES);
        if (more) {
            const int kt = (t + 1) * 16;
            const float* ar = A + (size_t)rl * LDA + kt + kh;
            na0 = *(const float4*)(ar);
            na1 = *(const float4*)(ar + 4);
            if (tid < 256) {
                const float4* src = (const float4*)(Bm + (size_t)kt * 64) + tid;
                nbv = SPATIAL ? __ldcg(src) : *src;
            }
        }

        #pragma unroll
        for (int k = 0; k < 16; k++) {
            float4 aa = *(const float4*)&As[p][k][n0];
            float4 b0 = *(const float4*)&Bs[p][k][t0];
            float4 b1 = *(const float4*)&Bs[p][k][t0 + 4];
            float a[4] = {aa.x, aa.y, aa.z, aa.w};
            float b[8] = {b0.x, b0.y, b0.z, b0.w, b1.x, b1.y, b1.z, b1.w};
            #pragma unroll
            for (int i = 0; i < 4; i++)
                #pragma unroll
                for (int j = 0; j < 8; j++)
                    av[i][j] = fmaf(a[i], b[j], av[i][j]);
        }

        if (more) {
            const int q = p ^ 1;       // writes to other buffer: no race with readers of p
            As[q][kh + 0][rl] = na0.x; As[q][kh + 1][rl] = na0.y;
            As[q][kh + 2][rl] = na0.z; As[q][kh + 3][rl] = na0.w;
            As[q][kh + 4][rl] = na1.x; As[q][kh + 5][rl] = na1.y;
            As[q][kh + 6][rl] = na1.z; As[q][kh + 7][rl] = na1.w;
            if (tid < 256) ((float4*)&Bs[q][0][0])[tid] = nbv;
            __syncthreads();
            p = q;
        }
    }

    // ---- epilogue: partial dots + norm from registers ----
    float pd1 = 0.f, pd2 = 0.f, pr2 = 0.f;
    float4 lv[4][2];
    #pragma unroll
    for (int i = 0; i < 4; i++) {
        size_t base = (size_t)(n0 + i) * 64 + t0;
        lv[i][0] = *(const float4*)(lasth + base);
        lv[i][1] = *(const float4*)(lasth + base + 4);
        const float* lp = (const float*)&lv[i][0];
        #pragma unroll
        for (int j = 0; j < 8; j++) {
            pd1 = fmaf(av[i][j], lp[j], pd1);
            pr2 = fmaf(av[i][j], av[i][j], pr2);
        }
        if (has_sec) {
            float4 s0 = *(const float4*)(sech + base);
            float4 s1 = *(const float4*)(sech + base + 4);
            float s[8] = {s0.x, s0.y, s0.z, s0.w, s1.x, s1.y, s1.z, s1.w};
            #pragma unroll
            for (int j = 0; j < 8; j++) pd2 = fmaf(av[i][j], s[j], pd2);
        }
    }
    block_sum3(pd1, pd2, pr2, red);

    const int xb = phase * 4;
    if (tid == 0) { xch[xb + 0] = pd1; xch[xb + 1] = pd2; xch[xb + 2] = pr2; }
    CLUSTER_SYNC();
    float d1 = pd1 + dsmem_peer_f32(xch_addr + 4 * xb + 0, peer);
    float d2 = has_sec ? (pd2 + dsmem_peer_f32(xch_addr + 4 * xb + 4, peer)) : 0.f;
    float r2 = pr2 + dsmem_peer_f32(xch_addr + 4 * xb + 8, peer);
    float n2 = r2 - d1 * d1 - d2 * d2;
    float inv = 1.f / fmaxf(sqrtf(fmaxf(n2, 0.f)), 1e-8f);

    // ---- write normalized dst + acc update from registers ----
    #pragma unroll
    for (int i = 0; i < 4; i++) {
        size_t base = (size_t)(n0 + i) * 64 + t0;
        const float* lp = (const float*)&lv[i][0];
        float v[8];
        if (has_sec) {
            float4 s0 = *(const float4*)(sech + base);
            float4 s1 = *(const float4*)(sech + base + 4);
            float s[8] = {s0.x, s0.y, s0.z, s0.w, s1.x, s1.y, s1.z, s1.w};
            #pragma unroll
            for (int j = 0; j < 8; j++) v[j] = (av[i][j] - d1 * lp[j] - d2 * s[j]) * inv;
        } else {
            #pragma unroll
            for (int j = 0; j < 8; j++) v[j] = (av[i][j] - d1 * lp[j]) * inv;
        }
        *(float4*)(dsth + base)     = make_float4(v[0], v[1], v[2], v[3]);
        *(float4*)(dsth + base + 4) = make_float4(v[4], v[5], v[6], v[7]);
        float4 a0 = *(float4*)(acch + base);
        float4 a1 = *(float4*)(acch + base + 4);
        a0.x = fmaf(th, v[0], a0.x); a0.y = fmaf(th, v[1], a0.y);
        a0.z = fmaf(th, v[2], a0.z); a0.w = fmaf(th, v[3], a0.w);
        a1.x = fmaf(th, v[4], a1.x); a1.y = fmaf(th, v[5], a1.y);
        a1.z = fmaf(th, v[6], a1.z); a1.w = fmaf(th, v[7], a1.w);
        *(float4*)(acch + base)     = a0;
        *(float4*)(acch + base + 4) = a1;
    }
    if (trail) CLUSTER_SYNC();   // dst visibility to peer — only before spatial steps
}

// ---------------- main kernel: 2-CTA cluster per (b,f) slice ----------------
__global__ void __cluster_dims__(2, 1, 1) __launch_bounds__(NTHREADS, 1)
st_main_kernel(const float* __restrict__ x,
               const float* __restrict__ Ls,
               const float* __restrict__ Lt,
               const float* __restrict__ STE,
               const float* __restrict__ w_t1, const float* __restrict__ b_t1,
               const float* __restrict__ w_t2, const float* __restrict__ b_t2)
{
    __shared__ __align__(16) float As[2][16][M_HALF];
    __shared__ __align__(16) float Bs[2][16][64];
    __shared__ float red[3][32];
    __shared__ float theta_sm[66];
    __shared__ float h1_sm[60];
    __shared__ __align__(16) float xch[8];

    const int tid = threadIdx.x;
    const int slice = blockIdx.x >> 1;
    const uint32_t rank = blockIdx.x & 1;
    const uint32_t peer = rank ^ 1;
    const int b = slice >> 4;
    const uint32_t xch_addr = smem_u32(xch);
    const size_t hoff = (size_t)rank * HALF;

    const float* xs = x + (size_t)slice * SLICE;
    float* acc = g_acc + (size_t)slice * SLICE;
    float* bufp[5];
    #pragma unroll
    for (int i = 0; i < 5; i++) bufp[i] = g_bufs + ((size_t)slice * 5 + i) * SLICE;

    // ---- theta (tiny MLP on STE), redundantly per CTA ----
    if (tid < 60) {
        int o = tid / 10, s = tid % 10;
        float h = b_t1[o];
        #pragma unroll
        for (int t = 0; t < 5; t++) h = fmaf(w_t1[o * 5 + t], STE[b * 50 + t * 10 + s], h);
        h1_sm[o * 10 + s] = h;
    }
    __syncthreads();
    if (tid < 66) {
        int p = tid % 11, o = tid / 11;
        float h = b_t2[p];
        #pragma unroll
        for (int s = 0; s < 10; s++) h = fmaf(w_t2[p * 10 + s], h1_sm[o * 10 + s], h);
        theta_sm[o * 11 + p] = fmaxf(h, 0.f);   // flat r = o*11 + p matches M order
    }
    __syncthreads();

    // ---- m00 = x / fro(x);  acc = theta[0] * m00  (my half) ----
    float pnv = 0.f, z1 = 0.f, z2 = 0.f;
    const float4* x4 = (const float4*)(xs + hoff);
    for (int i = tid; i < HALF / 4; i += NTHREADS) {
        float4 v = x4[i];
        pnv += v.x * v.x + v.y * v.y + v.z * v.z + v.w * v.w;
    }
    block_sum3(pnv, z1, z2, red);
    if (tid == 0) xch[3] = pnv;
    CLUSTER_SYNC();
    float nv = pnv + dsmem_peer_f32(xch_addr + 12, peer);
    float inv = 1.f / fmaxf(sqrtf(nv), 1e-8f);
    float th0 = theta_sm[0];
    float4* b04 = (float4*)(bufp[0] + hoff);
    float4* a4 = (float4*)(acc + hoff);
    for (int i = tid; i < HALF / 4; i += NTHREADS) {
        float4 v = x4[i];
        v.x *= inv; v.y *= inv; v.z *= inv; v.w *= inv;
        b04[i] = v;
        a4[i] = make_float4(th0 * v.x, th0 * v.y, th0 * v.z, th0 * v.w);
    }
    __syncthreads();   // bufp[0] half complete before step 1 (temporal, own-half only)

    // ---- recurrence ----
    int last_s = 0, sec_s = -1, last_t = 0, sec_t = -1;
    int r = 1;
    for (int i = 0; i <= 10; i++) {
        if (i > 0) {
            int nb = 0;
            while (nb == last_s || nb == sec_s || nb == last_t || nb == sec_t) nb++;
            bool trail = (r % 6 == 5) && (r <= 59);
            basis_step<true>(Ls + (size_t)rank * M_HALF * 512,
                             bufp[last_s],
                             bufp[nb] + hoff,
                             bufp[last_s] + hoff,
                             (sec_s >= 0) ? bufp[sec_s] + hoff : nullptr,
                             theta_sm[r], acc + hoff, As, Bs, red,
                             xch, xch_addr, peer, r & 1, trail);
            sec_s = last_s; last_s = nb;
            last_t = nb; sec_t = -1;
            r++;
        }
        for (int j = 0; j < 5; j++) {
            int nb = 0;
            while (nb == last_s || nb == sec_s || nb == last_t || nb == sec_t) nb++;
            bool trail = (r % 6 == 5) && (r <= 59);
            basis_step<false>(bufp[last_t] + hoff,
                              Lt,
                              bufp[nb] + hoff,
                              bufp[last_t] + hoff,
                              (sec_t >= 0) ? bufp[sec_t] + hoff : nullptr,
                              theta_sm[r], acc + hoff, As, Bs, red,
                              xch, xch_addr, peer, r & 1, trail);
            sec_t = last_t; last_t = nb;
            r++;
        }
    }
}

// ---------------- output MLP + folded BatchNorm ----------------
__global__ __launch_bounds__(256)
void st_out_kernel(const float* __restrict__ x,
                   const float* __restrict__ w_mlp, const float* __restrict__ b_mlp,
                   const float* __restrict__ gamma, const float* __restrict__ beta,
                   const float* __restrict__ mean, const float* __restrict__ var,
                   float* __restrict__ out)
{
    __shared__ float ws[64][32];
    __shared__ float bs[64];
    const int tid = threadIdx.x;
    for (int i = tid; i < 64 * 32; i += 256) {
        int o = i >> 5;
        float invs = gamma[o] * rsqrtf(var[o] + 1e-5f);
        ws[o][i & 31] = w_mlp[i] * invs;
    }
    if (tid < 64) {
        float invs = gamma[tid] * rsqrtf(var[tid] + 1e-5f);
        bs[tid] = b_mlp[tid] * invs + beta[tid] - mean[tid] * invs;
    }
    __syncthreads();

    const int b = blockIdx.y;
    const int pt = blockIdx.x * 256 + tid;   // 0..32767

    float xv[16], av[16];
    #pragma unroll
    for (int c = 0; c < 16; c++) {
        xv[c] = x[((size_t)(b * 16 + c)) * SLICE + pt];
        av[c] = g_acc[((size_t)(b * 16 + c)) * SLICE + pt];
    }
    #pragma unroll
    for (int o = 0; o < 64; o++) {
        float s = bs[o];
        #pragma unroll
        for (int c = 0; c < 16; c++) {
            s = fmaf(ws[o][c], xv[c], s);
            s = fmaf(ws[o][16 + c], av[c], s);
        }
        out[((size_t)(b * 64 + o)) * SLICE + pt] = s;
    }
}

extern "C" void kernel_launch(void* const* d_in, const int* in_sizes, int n_in,
                              void* d_out, int out_size) {
    const float* x    = (const float*)d_in[0];
    const float* Ls   = (const float*)d_in[1];
    const float* Lt   = (const float*)d_in[2];
    const float* STE  = (const float*)d_in[3];
    const float* w_t1 = (const float*)d_in[4];
    const float* b_t1 = (const float*)d_in[5];
    const float* w_t2 = (const float*)d_in[6];
    const float* b_t2 = (const float*)d_in[7];
    const float* w_mlp = (const float*)d_in[8];
    const float* b_mlp = (const float*)d_in[9];
    const float* gamma = (const float*)d_in[10];
    const float* beta  = (const float*)d_in[11];
    const float* mean  = (const float*)d_in[12];
    const float* var   = (const float*)d_in[13];
    float* out = (float*)d_out;

    st_main_kernel<<<NSLICES * 2, NTHREADS>>>(x, Ls, Lt, STE, w_t1, b_t1, w_t2, b_t2);
    st_out_kernel<<<dim3(128, 4), 256>>>(x, w_mlp, b_mlp, gamma, beta, mean, var, out);
}